// round 10
// baseline (speedup 1.0000x reference)
#include <cuda_runtime.h>
#include <cstdint>

#define IMG_H 2048
#define IMG_W 4096
#define IMG_C 3

#define TILE_H 16
#define TILE_W 64
#define TILES_X (IMG_W / TILE_W)   // 64
#define TILES_Y (IMG_H / TILE_H)   // 128
#define R_MAX 24
#define PX_MAX 80
#define SPITCH (3 * PX_MAX)        // 240 floats per staged row

// Keys cubic (a=-0.5) tap weights for offsets -1..2 at fractional t in [0,1].
__device__ __forceinline__ void cubic_w(float t, float& w0, float& w1, float& w2, float& w3) {
    float s = 1.0f - t;
    w0 = -0.5f * t * s * s;
    w1 = fmaf(fmaf(1.5f, t, -2.5f), t * t, 1.0f);
    w2 = t * fmaf(fmaf(-1.5f, t, 2.0f), t, 0.5f);
    w3 = -0.5f * t * t * s;
}

// 3 clamped-accumulated spline weights for output index i (3 control points).
__device__ __forceinline__ void spline3(int i, int n_out, float b[3]) {
    float u = ((float)i * 2.0f) / (float)(n_out - 1);
    float fj = floorf(u);
    int j0 = (int)fj;
    float t = u - fj;
    float w0, w1, w2, w3;
    cubic_w(t, w0, w1, w2, w3);
    float wv[4] = {w0, w1, w2, w3};
    b[0] = 0.0f; b[1] = 0.0f; b[2] = 0.0f;
#pragma unroll
    for (int a = 0; a < 4; a++) {
        int idx = j0 - 1 + a;
        idx = idx < 0 ? 0 : (idx > 2 ? 2 : idx);
        if (idx == 0) b[0] += wv[a];
        else if (idx == 1) b[1] += wv[a];
        else b[2] += wv[a];
    }
}

__device__ __forceinline__ float wmin32(float v) {
#pragma unroll
    for (int off = 16; off >= 1; off >>= 1)
        v = fminf(v, __shfl_xor_sync(0xFFFFFFFFu, v, off));
    return v;
}
__device__ __forceinline__ float wmax32(float v) {
#pragma unroll
    for (int off = 16; off >= 1; off >>= 1)
        v = fmaxf(v, __shfl_xor_sync(0xFFFFFFFFu, v, off));
    return v;
}
__device__ __forceinline__ void imul(float alo, float ahi, float blo, float bhi,
                                     float& lo, float& hi) {
    float p1 = alo * blo, p2 = alo * bhi, p3 = ahi * blo, p4 = ahi * bhi;
    lo += fminf(fminf(p1, p2), fminf(p3, p4));
    hi += fmaxf(fmaxf(p1, p2), fmaxf(p3, p4));
}

__global__ void __launch_bounds__(256, 6)
warp_main(const float* __restrict__ img, const float* __restrict__ disp,
          float* __restrict__ out) {
    __shared__ float s_img[R_MAX * SPITCH];      // 23040 B
    __shared__ float4 s_bx[TILE_W];              // 1024 B
    __shared__ float4 s_rowD[TILE_H][2];         // 512 B

    int tx = blockIdx.x, ty = blockIdx.y;
    int tid = threadIdx.x;

    // Phase A: compute spline factors in-block (fused former prep_kernel).
    if (tid < TILE_W) {
        float bx[3];
        spline3(tx * TILE_W + tid, IMG_W, bx);
        s_bx[tid] = make_float4(bx[0], bx[1], bx[2], 0.0f);
    } else if (tid < TILE_W + TILE_H) {
        int r = tid - TILE_W;
        float by[3];
        spline3(ty * TILE_H + r, IMG_H, by);
#pragma unroll
        for (int d = 0; d < 2; d++) {
            float v0 = by[0] * (5.0f * __ldg(disp + d * 9 + 0))
                     + by[1] * (5.0f * __ldg(disp + d * 9 + 3))
                     + by[2] * (5.0f * __ldg(disp + d * 9 + 6));
            float v1 = by[0] * (5.0f * __ldg(disp + d * 9 + 1))
                     + by[1] * (5.0f * __ldg(disp + d * 9 + 4))
                     + by[2] * (5.0f * __ldg(disp + d * 9 + 7));
            float v2 = by[0] * (5.0f * __ldg(disp + d * 9 + 2))
                     + by[1] * (5.0f * __ldg(disp + d * 9 + 5))
                     + by[2] * (5.0f * __ldg(disp + d * 9 + 8));
            s_rowD[r][d] = make_float4(v0, v1, v2, 0.0f);
        }
    }
    __syncthreads();

    // Phase B: every warp redundantly computes the tile's conservative sample
    // window via interval arithmetic (disp = sum_k ry_k * bx_k). All lanes end
    // with identical row0/px0/nrows/npx in registers -> no barrier, no smem.
    int row0, px0, nrows, npx;
    {
        int lane = tid & 31;
        float4 b1 = s_bx[lane], b2 = s_bx[lane + 32];
        float bxmn[3] = {fminf(b1.x, b2.x), fminf(b1.y, b2.y), fminf(b1.z, b2.z)};
        float bxmx[3] = {fmaxf(b1.x, b2.x), fmaxf(b1.y, b2.y), fmaxf(b1.z, b2.z)};
        float4 ryv = s_rowD[lane & (TILE_H - 1)][0];
        float4 rxv = s_rowD[lane & (TILE_H - 1)][1];
        float rymn[3] = {ryv.x, ryv.y, ryv.z}, rymx[3] = {ryv.x, ryv.y, ryv.z};
        float rxmn[3] = {rxv.x, rxv.y, rxv.z}, rxmx[3] = {rxv.x, rxv.y, rxv.z};
#pragma unroll
        for (int k = 0; k < 3; k++) {
            bxmn[k] = wmin32(bxmn[k]); bxmx[k] = wmax32(bxmx[k]);
            rymn[k] = wmin32(rymn[k]); rymx[k] = wmax32(rymx[k]);
            rxmn[k] = wmin32(rxmn[k]); rxmx[k] = wmax32(rxmx[k]);
        }
        float dylo = 0.f, dyhi = 0.f, dxlo = 0.f, dxhi = 0.f;
#pragma unroll
        for (int k = 0; k < 3; k++) {
            imul(rymn[k], rymx[k], bxmn[k], bxmx[k], dylo, dyhi);
            imul(rxmn[k], rxmx[k], bxmn[k], bxmx[k], dxlo, dxhi);
        }
        const float pad = 0.01f;
        int iy_lo = (int)floorf((float)(ty * TILE_H) + dylo - pad);
        int iy_hi = (int)floorf((float)(ty * TILE_H + TILE_H - 1) + dyhi + pad);
        int ix_lo = (int)floorf((float)(tx * TILE_W) + dxlo - pad);
        int ix_hi = (int)floorf((float)(tx * TILE_W + TILE_W - 1) + dxhi + pad);
        row0 = iy_lo - 1;
        nrows = iy_hi - iy_lo + 4;
        px0 = (ix_lo - 1) & ~3;           // 4-px align -> float idx mult of 4
        npx = ix_hi + 3 - px0;
        bool okw = (ix_lo >= 1) && (row0 >= 0) && (row0 + nrows <= IMG_H)
                && (px0 >= 0) && (px0 + npx <= IMG_W - 1)   // vec4 tail slack
                && (nrows <= R_MAX) && (npx <= PX_MAX);
        if (!okw) nrows = 0;
    }
    bool ok = nrows > 0;

    // Phase C: cooperative stage of the image window (vec4, coalesced)
    if (ok) {
        int n4 = (3 * npx + 3) >> 2;
        int total = nrows * n4;
        for (int idx = tid; idx < total; idx += 256) {
            int r = idx / n4;
            int i = idx - r * n4;
            const float4* src = reinterpret_cast<const float4*>(
                img + ((size_t)(row0 + r) * IMG_W + px0) * IMG_C);
            reinterpret_cast<float4*>(s_img + r * SPITCH)[i] = __ldg(src + i);
        }
    }
    __syncthreads();

    // Phase D: per-pixel gather (4 px per thread, one pixel in flight at a
    // time — unroll 1 keeps regs within the 42 budget; latency hiding comes
    // from occupancy + ILP inside the 12-LDS chain).
    int lc = tid & (TILE_W - 1);
    int lr0 = tid >> 6;                 // 0..3
    int x = tx * TILE_W + lc;
    float4 bx = s_bx[lc];

#pragma unroll 1
    for (int k = 0; k < 4; k++) {
        int ly = lr0 * 4 + k;           // warp-uniform row
        int y = ty * TILE_H + ly;
        float4 ry = s_rowD[ly][0];
        float4 rx = s_rowD[ly][1];

        float dispy = fmaf(ry.x, bx.x, fmaf(ry.y, bx.y, ry.z * bx.z));
        float dispx = fmaf(rx.x, bx.x, fmaf(rx.y, bx.y, rx.z * bx.z));

        float yy = (float)y + dispy;
        float xx = (float)x + dispx;
        float fy = floorf(yy), fx = floorf(xx);
        int iy0 = (int)fy, ix0 = (int)fx;
        float tyf = yy - fy, txf = xx - fx;

        float wy0, wy1, wy2, wy3, wx0, wx1, wx2, wx3;
        cubic_w(tyf, wy0, wy1, wy2, wy3);
        cubic_w(txf, wx0, wx1, wx2, wx3);
        float wyA[4] = {wy0, wy1, wy2, wy3};

        float accr = 0.0f, accg = 0.0f, accb = 0.0f;

        if (ok) {
            // Staged gather: conflict-free scalar LDS (stride-3 bank-injective).
            int lrow = iy0 - 1 - row0;
            lrow = min(max(lrow, 0), nrows - 4);            // belt-and-braces
            int lcol = (ix0 - 1 - px0) * 3;
            lcol = min(max(lcol, 0), 3 * npx - 12);
            const float* p = s_img + lrow * SPITCH + lcol;
#pragma unroll
            for (int a = 0; a < 4; a++) {
                const float* q = p + a * SPITCH;
                float sr = fmaf(wx3, q[9],  fmaf(wx2, q[6], fmaf(wx1, q[3], wx0 * q[0])));
                float sg = fmaf(wx3, q[10], fmaf(wx2, q[7], fmaf(wx1, q[4], wx0 * q[1])));
                float sb = fmaf(wx3, q[11], fmaf(wx2, q[8], fmaf(wx1, q[5], wx0 * q[2])));
                accr = fmaf(wyA[a], sr, accr);
                accg = fmaf(wyA[a], sg, accg);
                accb = fmaf(wyA[a], sb, accb);
            }
        } else {
            // Fallback (border / oversized-window tiles): clamped scalar taps.
            float wxA[4] = {wx0, wx1, wx2, wx3};
#pragma unroll
            for (int a = 0; a < 4; a++) {
                int tyc = iy0 - 1 + a;
                tyc = min(max(tyc, 0), IMG_H - 1);
                int rowb = tyc * IMG_W * IMG_C;
#pragma unroll
                for (int b = 0; b < 4; b++) {
                    int txc = ix0 - 1 + b;
                    txc = min(max(txc, 0), IMG_W - 1);
                    int p = rowb + txc * IMG_C;
                    float w = wyA[a] * wxA[b];
                    accr = fmaf(w, __ldg(img + p),     accr);
                    accg = fmaf(w, __ldg(img + p + 1), accg);
                    accb = fmaf(w, __ldg(img + p + 2), accb);
                }
            }
        }

        int o = (y * IMG_W + x) * IMG_C;
        out[o]     = accr;
        out[o + 1] = accg;
        out[o + 2] = accb;
    }
}

extern "C" void kernel_launch(void* const* d_in, const int* in_sizes, int n_in,
                              void* d_out, int out_size) {
    const float* img  = (const float*)d_in[0];
    const float* disp = (const float*)d_in[1];
    if (n_in >= 2 && in_sizes[0] == 18) {  // defensive: swap if order differs
        img  = (const float*)d_in[1];
        disp = (const float*)d_in[0];
    }

    dim3 grid(TILES_X, TILES_Y);
    warp_main<<<grid, 256>>>(img, disp, (float*)d_out);
}

// round 11
// speedup vs baseline: 1.1041x; 1.1041x over previous
#include <cuda_runtime.h>
#include <cstdint>

#define IMG_H 2048
#define IMG_W 4096
#define IMG_C 3

#define TILE_H 16
#define TILE_W 64
#define TILES_X (IMG_W / TILE_W)   // 64
#define TILES_Y (IMG_H / TILE_H)   // 128
#define R_MAX 24
#define PX_MAX 80
#define SPITCH (3 * PX_MAX)        // 240 floats per staged row

// Keys cubic (a=-0.5) tap weights for offsets -1..2 at fractional t in [0,1].
__device__ __forceinline__ void cubic_w(float t, float& w0, float& w1, float& w2, float& w3) {
    float s = 1.0f - t;
    w0 = -0.5f * t * s * s;
    w1 = fmaf(fmaf(1.5f, t, -2.5f), t * t, 1.0f);
    w2 = t * fmaf(fmaf(-1.5f, t, 2.0f), t, 0.5f);
    w3 = -0.5f * t * t * s;
}

// 3 clamped-accumulated spline weights for output index i (3 control points).
__device__ __forceinline__ void spline3(int i, int n_out, float b[3]) {
    float u = ((float)i * 2.0f) / (float)(n_out - 1);
    float fj = floorf(u);
    int j0 = (int)fj;
    float t = u - fj;
    float w0, w1, w2, w3;
    cubic_w(t, w0, w1, w2, w3);
    float wv[4] = {w0, w1, w2, w3};
    b[0] = 0.0f; b[1] = 0.0f; b[2] = 0.0f;
#pragma unroll
    for (int a = 0; a < 4; a++) {
        int idx = j0 - 1 + a;
        idx = idx < 0 ? 0 : (idx > 2 ? 2 : idx);
        if (idx == 0) b[0] += wv[a];
        else if (idx == 1) b[1] += wv[a];
        else b[2] += wv[a];
    }
}

__device__ __forceinline__ float wmin32(float v) {
#pragma unroll
    for (int off = 16; off >= 1; off >>= 1)
        v = fminf(v, __shfl_xor_sync(0xFFFFFFFFu, v, off));
    return v;
}
__device__ __forceinline__ float wmax32(float v) {
#pragma unroll
    for (int off = 16; off >= 1; off >>= 1)
        v = fmaxf(v, __shfl_xor_sync(0xFFFFFFFFu, v, off));
    return v;
}
__device__ __forceinline__ void imul(float alo, float ahi, float blo, float bhi,
                                     float& lo, float& hi) {
    float p1 = alo * blo, p2 = alo * bhi, p3 = ahi * blo, p4 = ahi * bhi;
    lo += fminf(fminf(p1, p2), fminf(p3, p4));
    hi += fmaxf(fmaxf(p1, p2), fmaxf(p3, p4));
}

__global__ void __launch_bounds__(256, 6)
warp_main(const float* __restrict__ img, const float* __restrict__ disp,
          float* __restrict__ out) {
    __shared__ float s_img[R_MAX * SPITCH];      // 23040 B
    __shared__ float4 s_bx[TILE_W];              // 1024 B
    __shared__ float4 s_rowD[TILE_H][2];         // 512 B
    __shared__ int4 s_meta;                      // row0, px0, nrows(0=fallback), npx

    int tx = blockIdx.x, ty = blockIdx.y;
    int tid = threadIdx.x;

    // Phase A: compute spline factors in-block (fused former prep_kernel).
    if (tid < TILE_W) {
        float bx[3];
        spline3(tx * TILE_W + tid, IMG_W, bx);
        s_bx[tid] = make_float4(bx[0], bx[1], bx[2], 0.0f);
    } else if (tid < TILE_W + TILE_H) {
        int r = tid - TILE_W;
        float by[3];
        spline3(ty * TILE_H + r, IMG_H, by);
#pragma unroll
        for (int d = 0; d < 2; d++) {
            float v0 = by[0] * (5.0f * __ldg(disp + d * 9 + 0))
                     + by[1] * (5.0f * __ldg(disp + d * 9 + 3))
                     + by[2] * (5.0f * __ldg(disp + d * 9 + 6));
            float v1 = by[0] * (5.0f * __ldg(disp + d * 9 + 1))
                     + by[1] * (5.0f * __ldg(disp + d * 9 + 4))
                     + by[2] * (5.0f * __ldg(disp + d * 9 + 7));
            float v2 = by[0] * (5.0f * __ldg(disp + d * 9 + 2))
                     + by[1] * (5.0f * __ldg(disp + d * 9 + 5))
                     + by[2] * (5.0f * __ldg(disp + d * 9 + 8));
            s_rowD[r][d] = make_float4(v0, v1, v2, 0.0f);
        }
    }
    __syncthreads();

    // Phase B: warp 0 ONLY computes the tile's conservative sample window via
    // interval arithmetic (disp = sum_k ry_k * bx_k); result broadcast through
    // s_meta. (Redundant all-warp reduction measured WORSE: 90 SHFL + 90 FMNMX
    // per warp vs one 7-cyc barrier — R10 post-mortem.)
    if (tid < 32) {
        float4 b1 = s_bx[tid], b2 = s_bx[tid + 32];
        float bxmn[3] = {fminf(b1.x, b2.x), fminf(b1.y, b2.y), fminf(b1.z, b2.z)};
        float bxmx[3] = {fmaxf(b1.x, b2.x), fmaxf(b1.y, b2.y), fmaxf(b1.z, b2.z)};
        float4 ryv = s_rowD[tid & (TILE_H - 1)][0];
        float4 rxv = s_rowD[tid & (TILE_H - 1)][1];
        float rymn[3] = {ryv.x, ryv.y, ryv.z}, rymx[3] = {ryv.x, ryv.y, ryv.z};
        float rxmn[3] = {rxv.x, rxv.y, rxv.z}, rxmx[3] = {rxv.x, rxv.y, rxv.z};
#pragma unroll
        for (int k = 0; k < 3; k++) {
            bxmn[k] = wmin32(bxmn[k]); bxmx[k] = wmax32(bxmx[k]);
            rymn[k] = wmin32(rymn[k]); rymx[k] = wmax32(rymx[k]);
            rxmn[k] = wmin32(rxmn[k]); rxmx[k] = wmax32(rxmx[k]);
        }
        if (tid == 0) {
            float dylo = 0.f, dyhi = 0.f, dxlo = 0.f, dxhi = 0.f;
#pragma unroll
            for (int k = 0; k < 3; k++) {
                imul(rymn[k], rymx[k], bxmn[k], bxmx[k], dylo, dyhi);
                imul(rxmn[k], rxmx[k], bxmn[k], bxmx[k], dxlo, dxhi);
            }
            const float pad = 0.01f;
            int iy_lo = (int)floorf((float)(ty * TILE_H) + dylo - pad);
            int iy_hi = (int)floorf((float)(ty * TILE_H + TILE_H - 1) + dyhi + pad);
            int ix_lo = (int)floorf((float)(tx * TILE_W) + dxlo - pad);
            int ix_hi = (int)floorf((float)(tx * TILE_W + TILE_W - 1) + dxhi + pad);
            int row0 = iy_lo - 1;
            int nrows = iy_hi - iy_lo + 4;
            int px0 = (ix_lo - 1) & ~3;       // 4-px align -> float idx mult of 4
            int npx = ix_hi + 3 - px0;
            bool ok = (ix_lo >= 1) && (row0 >= 0) && (row0 + nrows <= IMG_H)
                   && (px0 >= 0) && (px0 + npx <= IMG_W - 1)  // vec4 tail slack
                   && (nrows <= R_MAX) && (npx <= PX_MAX);
            s_meta = make_int4(row0, px0, ok ? nrows : 0, npx);
        }
    }
    __syncthreads();

    int row0 = s_meta.x, px0 = s_meta.y, nrows = s_meta.z, npx = s_meta.w;
    bool ok = nrows > 0;

    // Phase C: cooperative stage of the image window (vec4, coalesced)
    if (ok) {
        int n4 = (3 * npx + 3) >> 2;
        int total = nrows * n4;
        for (int idx = tid; idx < total; idx += 256) {
            int r = idx / n4;
            int i = idx - r * n4;
            const float4* src = reinterpret_cast<const float4*>(
                img + ((size_t)(row0 + r) * IMG_W + px0) * IMG_C);
            reinterpret_cast<float4*>(s_img + r * SPITCH)[i] = __ldg(src + i);
        }
    }
    __syncthreads();

    // Phase D: per-pixel gather (4 px per thread, one pixel in flight at a
    // time — unroll 1 keeps regs within the 42 budget; latency hiding comes
    // from occupancy + ILP inside the 12-LDS chain).
    int lc = tid & (TILE_W - 1);
    int lr0 = tid >> 6;                 // 0..3
    int x = tx * TILE_W + lc;
    float4 bx = s_bx[lc];

#pragma unroll 1
    for (int k = 0; k < 4; k++) {
        int ly = lr0 * 4 + k;           // warp-uniform row
        int y = ty * TILE_H + ly;
        float4 ry = s_rowD[ly][0];
        float4 rx = s_rowD[ly][1];

        float dispy = fmaf(ry.x, bx.x, fmaf(ry.y, bx.y, ry.z * bx.z));
        float dispx = fmaf(rx.x, bx.x, fmaf(rx.y, bx.y, rx.z * bx.z));

        float yy = (float)y + dispy;
        float xx = (float)x + dispx;
        float fy = floorf(yy), fx = floorf(xx);
        int iy0 = (int)fy, ix0 = (int)fx;
        float tyf = yy - fy, txf = xx - fx;

        float wy0, wy1, wy2, wy3, wx0, wx1, wx2, wx3;
        cubic_w(tyf, wy0, wy1, wy2, wy3);
        cubic_w(txf, wx0, wx1, wx2, wx3);
        float wyA[4] = {wy0, wy1, wy2, wy3};

        float accr = 0.0f, accg = 0.0f, accb = 0.0f;

        if (ok) {
            // Staged gather: conflict-free scalar LDS (stride-3 bank-injective).
            int lrow = iy0 - 1 - row0;
            lrow = min(max(lrow, 0), nrows - 4);            // belt-and-braces
            int lcol = (ix0 - 1 - px0) * 3;
            lcol = min(max(lcol, 0), 3 * npx - 12);
            const float* p = s_img + lrow * SPITCH + lcol;
#pragma unroll
            for (int a = 0; a < 4; a++) {
                const float* q = p + a * SPITCH;
                float sr = fmaf(wx3, q[9],  fmaf(wx2, q[6], fmaf(wx1, q[3], wx0 * q[0])));
                float sg = fmaf(wx3, q[10], fmaf(wx2, q[7], fmaf(wx1, q[4], wx0 * q[1])));
                float sb = fmaf(wx3, q[11], fmaf(wx2, q[8], fmaf(wx1, q[5], wx0 * q[2])));
                accr = fmaf(wyA[a], sr, accr);
                accg = fmaf(wyA[a], sg, accg);
                accb = fmaf(wyA[a], sb, accb);
            }
        } else {
            // Fallback (border / oversized-window tiles): clamped scalar taps.
            float wxA[4] = {wx0, wx1, wx2, wx3};
#pragma unroll
            for (int a = 0; a < 4; a++) {
                int tyc = iy0 - 1 + a;
                tyc = min(max(tyc, 0), IMG_H - 1);
                int rowb = tyc * IMG_W * IMG_C;
#pragma unroll
                for (int b = 0; b < 4; b++) {
                    int txc = ix0 - 1 + b;
                    txc = min(max(txc, 0), IMG_W - 1);
                    int p = rowb + txc * IMG_C;
                    float w = wyA[a] * wxA[b];
                    accr = fmaf(w, __ldg(img + p),     accr);
                    accg = fmaf(w, __ldg(img + p + 1), accg);
                    accb = fmaf(w, __ldg(img + p + 2), accb);
                }
            }
        }

        int o = (y * IMG_W + x) * IMG_C;
        out[o]     = accr;
        out[o + 1] = accg;
        out[o + 2] = accb;
    }
}

extern "C" void kernel_launch(void* const* d_in, const int* in_sizes, int n_in,
                              void* d_out, int out_size) {
    const float* img  = (const float*)d_in[0];
    const float* disp = (const float*)d_in[1];
    if (n_in >= 2 && in_sizes[0] == 18) {  // defensive: swap if order differs
        img  = (const float*)d_in[1];
        disp = (const float*)d_in[0];
    }

    dim3 grid(TILES_X, TILES_Y);
    warp_main<<<grid, 256>>>(img, disp, (float*)d_out);
}